// round 5
// baseline (speedup 1.0000x reference)
#include <cuda_runtime.h>
#include <math_constants.h>

#define NN 512
#define DIMX 256
#define NH 8
#define DH 64
#define INNER 512
#define NR 66
#define PI_F 3.14159265358979f
#define SCALE_F 0.125f
#define INV_NORM (1.0f/51.0f)
#define DSTEP_F (7.0f*PI_F/15.0f)
#define KSPLIT 4

// ---------------- scratch ----------------
__device__ float g_q [NN*INNER];
__device__ float g_kc[NN*INNER];
__device__ float g_v [NN*INNER];
__device__ float g_P [NN*NR*NH];                 // [i][r][h]
__device__ float g_sc[(size_t)NN*NH*NN];         // scores/attn, [i][h][j]
__device__ float g_ao[KSPLIT*(size_t)NN*INNER];  // split-K partials [s][i][hd]

// ---------------- K1: QKV projections, 32x64 tiles, K-chunk 32, reg prefetch --
// grid (8 ntile, 16 mtile, 3), block 256, thread tile 2x4
__global__ void __launch_bounds__(256) qkv_kernel(const float* __restrict__ x,
                           const float* __restrict__ Wq,
                           const float* __restrict__ Wk,
                           const float* __restrict__ Wv) {
    __shared__ float As[32][34];   // [k][m]
    __shared__ float Bs[32][68];   // [k][n]
    const float* W = (blockIdx.z == 0) ? Wq : ((blockIdx.z == 1) ? Wk : Wv);
    float* out = (blockIdx.z == 0) ? g_q : ((blockIdx.z == 1) ? g_kc : g_v);
    const int n0 = blockIdx.x * 64, m0 = blockIdx.y * 32;
    const int tid = threadIdx.x, tx = tid & 15, ty = tid >> 4;
    const int am = tid >> 3, ac = tid & 7;   // A: row m0+am, k=ac*4
    const int bk = tid >> 3, bc = tid & 7;   // B: k-row bk, n=bc*4 (+32)
    const float* xrow  = x + (size_t)(m0 + am) * DIMX;
    const float* wbase = W + n0;

    float4 ra  = *(const float4*)&xrow[ac * 4];
    float4 rb0 = *(const float4*)&wbase[(size_t)bk * INNER + bc * 4];
    float4 rb1 = *(const float4*)&wbase[(size_t)bk * INNER + bc * 4 + 32];

    float acc[2][4] = {};
    for (int c = 0; c < 8; c++) {
        As[ac*4+0][am] = ra.x; As[ac*4+1][am] = ra.y;
        As[ac*4+2][am] = ra.z; As[ac*4+3][am] = ra.w;
        *(float4*)&Bs[bk][bc*4]      = rb0;
        *(float4*)&Bs[bk][bc*4 + 32] = rb1;
        __syncthreads();
        if (c < 7) {
            int k0 = (c + 1) * 32;
            ra  = *(const float4*)&xrow[k0 + ac * 4];
            rb0 = *(const float4*)&wbase[(size_t)(k0 + bk) * INNER + bc * 4];
            rb1 = *(const float4*)&wbase[(size_t)(k0 + bk) * INNER + bc * 4 + 32];
        }
#pragma unroll
        for (int kk = 0; kk < 32; kk++) {
            float2 a = *(const float2*)&As[kk][ty * 2];
            float4 b = *(const float4*)&Bs[kk][tx * 4];
            acc[0][0] += a.x * b.x; acc[0][1] += a.x * b.y;
            acc[0][2] += a.x * b.z; acc[0][3] += a.x * b.w;
            acc[1][0] += a.y * b.x; acc[1][1] += a.y * b.y;
            acc[1][2] += a.y * b.z; acc[1][3] += a.y * b.w;
        }
        __syncthreads();
    }
#pragma unroll
    for (int m = 0; m < 2; m++) {
        float4 r = make_float4(acc[m][0], acc[m][1], acc[m][2], acc[m][3]);
        *(float4*)&out[(size_t)(m0 + ty * 2 + m) * INNER + n0 + tx * 4] = r;
    }
}

// ---------------- K2: combined content scores (z<8) + P (z==8) --------
__global__ void __launch_bounds__(256) cs_p_kernel(const float* __restrict__ Wk) {
    __shared__ float sm[2 * 64 * 68];
    const int tid = threadIdx.x;
    if (blockIdx.z < 8) {
        float (*Qs)[68] = (float(*)[68])sm;
        float (*Ks)[68] = (float(*)[68])(sm + 64 * 68);
        const int h = blockIdx.z;
        const int j0 = blockIdx.x * 64, i0 = blockIdx.y * 64;
        const int row = tid >> 2, c = tid & 3;
        const float* qrow = g_q  + (size_t)(i0 + row) * INNER + h * DH;
        const float* krow = g_kc + (size_t)(j0 + row) * INNER + h * DH;
#pragma unroll
        for (int u = 0; u < 4; u++) {
            int d = (c + 4 * u) * 4;
            float4 qv = *(const float4*)&qrow[d];
            float4 kv = *(const float4*)&krow[d];
            Qs[d][row] = qv.x; Qs[d+1][row] = qv.y; Qs[d+2][row] = qv.z; Qs[d+3][row] = qv.w;
            Ks[d][row] = kv.x; Ks[d+1][row] = kv.y; Ks[d+2][row] = kv.z; Ks[d+3][row] = kv.w;
        }
        __syncthreads();
        const int tx = tid & 15, ty = tid >> 4;
        float acc[4][4] = {};
#pragma unroll
        for (int kk = 0; kk < 64; kk++) {
            float4 a = *(const float4*)&Qs[kk][ty * 4];
            float4 b = *(const float4*)&Ks[kk][tx * 4];
            float av[4] = {a.x, a.y, a.z, a.w};
            float bv[4] = {b.x, b.y, b.z, b.w};
#pragma unroll
            for (int m = 0; m < 4; m++)
#pragma unroll
                for (int n = 0; n < 4; n++) acc[m][n] += av[m] * bv[n];
        }
#pragma unroll
        for (int m = 0; m < 4; m++) {
            int i = i0 + ty * 4 + m;
            float4 r = make_float4(acc[m][0]*SCALE_F, acc[m][1]*SCALE_F,
                                   acc[m][2]*SCALE_F, acc[m][3]*SCALE_F);
            *(float4*)&g_sc[((size_t)i * NH + h) * NN + j0 + tx * 4] = r;
        }
    } else {
        float* qs = sm;
        const int i0 = (blockIdx.y * 8 + blockIdx.x) * 8;
        const float4* src = (const float4*)(g_q + (size_t)i0 * INNER);
#pragma unroll
        for (int u = 0; u < 4; u++) ((float4*)qs)[tid + u * 256] = src[tid + u * 256];
        __syncthreads();
        for (int tt = tid; tt < 528; tt += 256) {
            int r = tt >> 3, h = tt & 7;
            const float4* w4 = (const float4*)(Wk + (size_t)(DIMX + r) * INNER + h * DH);
            float acc[8] = {};
#pragma unroll
            for (int u = 0; u < 16; u++) {
                float4 wv = w4[u];
#pragma unroll
                for (int i = 0; i < 8; i++) {
                    float4 qv = *(const float4*)&qs[i * INNER + h * DH + u * 4];
                    acc[i] += wv.x*qv.x + wv.y*qv.y + wv.z*qv.z + wv.w*qv.w;
                }
            }
#pragma unroll
            for (int i = 0; i < 8; i++)
                g_P[((size_t)(i0 + i) * NR + r) * NH + h] = acc[i];
        }
    }
}

// ---------------- K3: RPE features + score add + softmax --------------
__global__ void __launch_bounds__(256, 3) rpe_softmax_kernel(const float* __restrict__ pos) {
    const int i = blockIdx.x;
    __shared__ float Ps[NR * NH];
    __shared__ float s_s[NH][NN];
    const int tid = threadIdx.x;
    for (int t = tid; t < NR * NH; t += 256) Ps[t] = g_P[(size_t)i * NR * NH + t];
    __syncthreads();

    const float2* pos2 = reinterpret_cast<const float2*>(pos);
    const float2 pq = pos2[i];
    const float4* Pt4 = reinterpret_cast<const float4*>(Ps);

    const int ja = tid, jb = tid + 256;
    const float2 pka = pos2[ja];
    const float2 pkb = pos2[jb];
    float dxa = (pka.x - pq.x) * INV_NORM; dxa = __fdividef(dxa, 1.f + fabsf(dxa));
    float dya = (pka.y - pq.y) * INV_NORM; dya = __fdividef(dya, 1.f + fabsf(dya));
    float dxb = (pkb.x - pq.x) * INV_NORM; dxb = __fdividef(dxb, 1.f + fabsf(dxb));
    float dyb = (pkb.y - pq.y) * INV_NORM; dyb = __fdividef(dyb, 1.f + fabsf(dyb));

    float A0[8] = {};
    float A1[8] = {};
    {
        float sa, ca, sb, cb, sda, cda, sdb, cdb;
        __sincosf(dxa * PI_F, &sa, &ca);  __sincosf(dxa * DSTEP_F, &sda, &cda);
        __sincosf(dxb * PI_F, &sb, &cb);  __sincosf(dxb * DSTEP_F, &sdb, &cdb);
#pragma unroll
        for (int k = 0; k < 16; k++) {
            float4 p0 = Pt4[2 * k],        p1 = Pt4[2 * k + 1];
            float4 q0 = Pt4[2 * (16 + k)], q1 = Pt4[2 * (16 + k) + 1];
            A0[0] += sa*p0.x + ca*q0.x;  A1[0] += sb*p0.x + cb*q0.x;
            A0[1] += sa*p0.y + ca*q0.y;  A1[1] += sb*p0.y + cb*q0.y;
            A0[2] += sa*p0.z + ca*q0.z;  A1[2] += sb*p0.z + cb*q0.z;
            A0[3] += sa*p0.w + ca*q0.w;  A1[3] += sb*p0.w + cb*q0.w;
            A0[4] += sa*p1.x + ca*q1.x;  A1[4] += sb*p1.x + cb*q1.x;
            A0[5] += sa*p1.y + ca*q1.y;  A1[5] += sb*p1.y + cb*q1.y;
            A0[6] += sa*p1.z + ca*q1.z;  A1[6] += sb*p1.z + cb*q1.z;
            A0[7] += sa*p1.w + ca*q1.w;  A1[7] += sb*p1.w + cb*q1.w;
            float ns = sa*cda + ca*sda, nc = ca*cda - sa*sda; sa = ns; ca = nc;
            ns = sb*cdb + cb*sdb; nc = cb*cdb - sb*sdb; sb = ns; cb = nc;
        }
        float4 p0 = Pt4[64], p1 = Pt4[65];
        A0[0] += dxa*p0.x; A0[1] += dxa*p0.y; A0[2] += dxa*p0.z; A0[3] += dxa*p0.w;
        A0[4] += dxa*p1.x; A0[5] += dxa*p1.y; A0[6] += dxa*p1.z; A0[7] += dxa*p1.w;
        A1[0] += dxb*p0.x; A1[1] += dxb*p0.y; A1[2] += dxb*p0.z; A1[3] += dxb*p0.w;
        A1[4] += dxb*p1.x; A1[5] += dxb*p1.y; A1[6] += dxb*p1.z; A1[7] += dxb*p1.w;
    }
    {
        float sa, ca, sb, cb, sda, cda, sdb, cdb;
        __sincosf(dya * PI_F, &sa, &ca);  __sincosf(dya * DSTEP_F, &sda, &cda);
        __sincosf(dyb * PI_F, &sb, &cb);  __sincosf(dyb * DSTEP_F, &sdb, &cdb);
#pragma unroll
        for (int k = 0; k < 16; k++) {
            float4 p0 = Pt4[2 * (33 + k)], p1 = Pt4[2 * (33 + k) + 1];
            float4 q0 = Pt4[2 * (49 + k)], q1 = Pt4[2 * (49 + k) + 1];
            A0[0] += sa*p0.x + ca*q0.x;  A1[0] += sb*p0.x + cb*q0.x;
            A0[1] += sa*p0.y + ca*q0.y;  A1[1] += sb*p0.y + cb*q0.y;
            A0[2] += sa*p0.z + ca*q0.z;  A1[2] += sb*p0.z + cb*q0.z;
            A0[3] += sa*p0.w + ca*q0.w;  A1[3] += sb*p0.w + cb*q0.w;
            A0[4] += sa*p1.x + ca*q1.x;  A1[4] += sb*p1.x + cb*q1.x;
            A0[5] += sa*p1.y + ca*q1.y;  A1[5] += sb*p1.y + cb*q1.y;
            A0[6] += sa*p1.z + ca*q1.z;  A1[6] += sb*p1.z + cb*q1.z;
            A0[7] += sa*p1.w + ca*q1.w;  A1[7] += sb*p1.w + cb*q1.w;
            float ns = sa*cda + ca*sda, nc = ca*cda - sa*sda; sa = ns; ca = nc;
            ns = sb*cdb + cb*sdb; nc = cb*cdb - sb*sdb; sb = ns; cb = nc;
        }
        float4 p0 = Pt4[130], p1 = Pt4[131];
        A0[0] += dya*p0.x; A0[1] += dya*p0.y; A0[2] += dya*p0.z; A0[3] += dya*p0.w;
        A0[4] += dya*p1.x; A0[5] += dya*p1.y; A0[6] += dya*p1.z; A0[7] += dya*p1.w;
        A1[0] += dyb*p0.x; A1[1] += dyb*p0.y; A1[2] += dyb*p0.z; A1[3] += dyb*p0.w;
        A1[4] += dyb*p1.x; A1[5] += dyb*p1.y; A1[6] += dyb*p1.z; A1[7] += dyb*p1.w;
    }

    const float* csrow = g_sc + (size_t)i * NH * NN;
#pragma unroll
    for (int h = 0; h < NH; h++) {
        s_s[h][ja] = csrow[h * NN + ja] + A0[h] * SCALE_F;
        s_s[h][jb] = csrow[h * NN + jb] + A1[h] * SCALE_F;
    }
    __syncthreads();

    const int w = tid >> 5, lane = tid & 31;
    float m = -CUDART_INF_F;
    for (int j = lane; j < NN; j += 32) m = fmaxf(m, s_s[w][j]);
#pragma unroll
    for (int o = 16; o; o >>= 1) m = fmaxf(m, __shfl_xor_sync(0xffffffffu, m, o));
    float sum = 0.f;
    for (int j = lane; j < NN; j += 32) {
        float e = __expf(s_s[w][j] - m);
        s_s[w][j] = e;
        sum += e;
    }
#pragma unroll
    for (int o = 16; o; o >>= 1) sum += __shfl_xor_sync(0xffffffffu, sum, o);
    const float inv = __fdividef(1.0f, sum);
    float* arow = g_sc + (size_t)i * NH * NN + (size_t)w * NN;
    for (int j = lane; j < NN; j += 32)
        arow[j] = s_s[w][j] * inv;
}

// ---------------- K4: attn @ V, 64x64 tile, 4x4 thread tile, split-K=4 --
__global__ void __launch_bounds__(256) av_kernel() {
    const int i0 = blockIdx.x * 64;   // 8
    const int h  = blockIdx.y;        // 8
    const int s  = blockIdx.z;        // KSPLIT
    const int kbase = s * (NN / KSPLIT);   // 128 per split
    __shared__ float At[32][68];      // [j][i] transposed
    __shared__ float Vt[32][68];      // [j][d]
    const int tid = threadIdx.x, tx = tid & 15, ty = tid >> 4;
    const int ai = tid >> 2, ac = tid & 3;
    const int vj = tid >> 3, vc = tid & 7;
    const float* arow = g_sc + ((size_t)(i0 + ai) * NH + h) * NN + kbase;
    const float* vcol = g_v + h * DH;

    float4 pa0 = *(const float4*)&arow[ac * 4];
    float4 pa1 = *(const float4*)&arow[ac * 4 + 16];
    float4 pv0 = *(const float4*)&vcol[(size_t)(kbase + vj) * INNER + vc * 4];
    float4 pv1 = *(const float4*)&vcol[(size_t)(kbase + vj) * INNER + vc * 4 + 32];

    float acc[4][4] = {};
    for (int c = 0; c < NN / KSPLIT / 32; c++) {   // 4 chunks of 32
        At[ac*4+0][ai] = pa0.x; At[ac*4+1][ai] = pa0.y;
        At[ac*4+2][ai] = pa0.z; At[ac*4+3][ai] = pa0.w;
        At[ac*4+16][ai] = pa1.x; At[ac*4+17][ai] = pa1.y;
        At[ac*4+18][ai] = pa1.z; At[ac*4+19][ai] = pa1.w;
        *(float4*)&Vt[vj][vc*4]      = pv0;
        *(float4*)&Vt[vj][vc*4 + 32] = pv1;
        __syncthreads();
        if (c < NN / KSPLIT / 32 - 1) {
            int k0 = (c + 1) * 32;
            pa0 = *(const float4*)&arow[k0 + ac * 4];
            pa1 = *(const float4*)&arow[k0 + ac * 4 + 16];
            pv0 = *(const float4*)&vcol[(size_t)(kbase + k0 + vj) * INNER + vc * 4];
            pv1 = *(const float4*)&vcol[(size_t)(kbase + k0 + vj) * INNER + vc * 4 + 32];
        }
#pragma unroll
        for (int kk = 0; kk < 32; kk++) {
            float4 a = *(const float4*)&At[kk][ty * 4];
            float4 b = *(const float4*)&Vt[kk][tx * 4];
            float av[4] = {a.x, a.y, a.z, a.w};
            float bv[4] = {b.x, b.y, b.z, b.w};
#pragma unroll
            for (int m = 0; m < 4; m++)
#pragma unroll
                for (int n = 0; n < 4; n++) acc[m][n] += av[m] * bv[n];
        }
        __syncthreads();
    }
#pragma unroll
    for (int m = 0; m < 4; m++) {
        float4 r = make_float4(acc[m][0], acc[m][1], acc[m][2], acc[m][3]);
        *(float4*)&g_ao[((size_t)s * NN + i0 + ty * 4 + m) * INNER + h * DH + tx * 4] = r;
    }
}

// ---------------- K5: out = (sum_s ao_s) @ Wo + bo, 16x64 tile ---------
__global__ void __launch_bounds__(256) out_kernel(const float* __restrict__ Wo,
                           const float* __restrict__ bo,
                           float* __restrict__ out) {
    const int n0 = blockIdx.x * 64;   // 4
    const int i0 = blockIdx.y * 16;   // 32
    __shared__ float At[64][17];      // [k][i]
    __shared__ float Bt[64][68];      // [k][n]
    const int tid = threadIdx.x;
    const int ti = tid >> 4, tn = tid & 15;
    const int ak = tid & 15;
    const int bkr = tid >> 2, bc2 = tid & 3;
    const float* arow = g_ao + (size_t)(i0 + ti) * INNER;
    const float* wrow = Wo + n0;

    float4 pa;
    {
        float4 u0 = *(const float4*)&arow[ak * 4];
        float4 u1 = *(const float4*)&arow[(size_t)NN * INNER + ak * 4];
        float4 u2 = *(const float4*)&arow[2 * (size_t)NN * INNER + ak * 4];
        float4 u3 = *(const float4*)&arow[3 * (size_t)NN * INNER + ak * 4];
        pa = make_float4(u0.x+u1.x+u2.x+u3.x, u0.y+u1.y+u2.y+u3.y,
                         u0.z+u1.z+u2.z+u3.z, u0.w+u1.w+u2.w+u3.w);
    }
    float4 pb[4];
#pragma unroll
    for (int u = 0; u < 4; u++)
        pb[u] = *(const float4*)&wrow[(size_t)bkr * DIMX + (bc2 + 4 * u) * 4];

    float acc[4] = {};
    for (int c = 0; c < 8; c++) {
        At[ak*4+0][ti] = pa.x; At[ak*4+1][ti] = pa.y;
        At[ak*4+2][ti] = pa.z; At[ak*4+3][ti] = pa.w;
#pragma unroll
        for (int u = 0; u < 4; u++)
            *(float4*)&Bt[bkr][(bc2 + 4 * u) * 4] = pb[u];
        __syncthreads();
        if (c < 7) {
            int k0 = (c + 1) * 64;
            float4 u0 = *(const float4*)&arow[k0 + ak * 4];
            float4 u1 = *(const float4*)&arow[(size_t)NN * INNER + k0 + ak * 4];
            float4 u2 = *(const float4*)&arow[2 * (size_t)NN * INNER + k0 + ak * 4];
            float4 u3 = *(const float4*)&arow[3 * (size_t)NN * INNER + k0 + ak * 4];
            pa = make_float4(u0.x+u1.x+u2.x+u3.x, u0.y+u1.y+u2.y+u3.y,
                             u0.z+u1.z+u2.z+u3.z, u0.w+u1.w+u2.w+u3.w);
#pragma unroll
            for (int u = 0; u < 4; u++)
                pb[u] = *(const float4*)&wrow[(size_t)(k0 + bkr) * DIMX + (bc2 + 4 * u) * 4];
        }
#pragma unroll
        for (int kk = 0; kk < 64; kk++) {
            float a = At[kk][ti];
            float4 b = *(const float4*)&Bt[kk][tn * 4];
            acc[0] += a * b.x; acc[1] += a * b.y;
            acc[2] += a * b.z; acc[3] += a * b.w;
        }
        __syncthreads();
    }
    float4 bv = *(const float4*)&bo[n0 + tn * 4];
    float4 r = make_float4(acc[0] + bv.x, acc[1] + bv.y, acc[2] + bv.z, acc[3] + bv.w);
    *(float4*)&out[(size_t)(i0 + ti) * DIMX + n0 + tn * 4] = r;
}

// ---------------- launch ----------------------------------------------
extern "C" void kernel_launch(void* const* d_in, const int* in_sizes, int n_in,
                              void* d_out, int out_size) {
    const float* x   = (const float*)d_in[0];
    const float* pos = (const float*)d_in[1];
    const float* Wq  = (const float*)d_in[2];
    const float* Wk  = (const float*)d_in[3];
    const float* Wv  = (const float*)d_in[4];
    const float* Wo  = (const float*)d_in[5];
    const float* bo  = (const float*)d_in[6];
    float* out = (float*)d_out;

    qkv_kernel<<<dim3(8, 16, 3), 256>>>(x, Wq, Wk, Wv);
    cs_p_kernel<<<dim3(8, 8, 9), 256>>>(Wk);
    rpe_softmax_kernel<<<512, 256>>>(pos);
    av_kernel<<<dim3(8, 8, KSPLIT), 256>>>();
    out_kernel<<<dim3(4, 32), 256>>>(Wo, bo, out);
}

// round 6
// speedup vs baseline: 1.1747x; 1.1747x over previous
#include <cuda_runtime.h>
#include <math_constants.h>

#define NN 512
#define DIMX 256
#define NH 8
#define DH 64
#define INNER 512
#define NR 66
#define PI_F 3.14159265358979f
#define SCALE_F 0.125f
#define INV_NORM (1.0f/51.0f)
#define DSTEP_F (7.0f*PI_F/15.0f)
#define KSPLIT 4

// ---------------- scratch ----------------
__device__ float g_q [NN*INNER];
__device__ float g_kc[NN*INNER];
__device__ float g_v [NN*INNER];
__device__ float g_P [NN*NR*NH];                 // [i][r][h]
__device__ float g_sc[(size_t)NN*NH*NN];         // scores/attn, [i][h][j]
__device__ float g_ao[KSPLIT*(size_t)NN*INNER];  // split-K partials [s][i][hd]

// ---------------- tf32 mma helpers ------------------------------------
static __device__ __forceinline__ unsigned f2t(float x) {
    unsigned u;
    asm("cvt.rna.tf32.f32 %0, %1;" : "=r"(u) : "f"(x));
    return u;
}
static __device__ __forceinline__ void mma8(float* c, const unsigned* a, const unsigned* b) {
    asm volatile(
        "mma.sync.aligned.m16n8k8.row.col.f32.tf32.tf32.f32 "
        "{%0,%1,%2,%3}, {%4,%5,%6,%7}, {%8,%9}, {%0,%1,%2,%3};"
        : "+f"(c[0]), "+f"(c[1]), "+f"(c[2]), "+f"(c[3])
        : "r"(a[0]), "r"(a[1]), "r"(a[2]), "r"(a[3]), "r"(b[0]), "r"(b[1]));
}
static __device__ __forceinline__ uint4 f2t4(float4 v) {
    return make_uint4(f2t(v.x), f2t(v.y), f2t(v.z), f2t(v.w));
}

// ---------------- K1: QKV projections (tf32 mma) -----------------------
// grid (8 ntile, 8 mtile, 3), block 128 (4 warps, 2x2), tile 64x64, K=256 in 4 chunks
__global__ void __launch_bounds__(128) qkv_kernel(const float* __restrict__ x,
                           const float* __restrict__ Wq,
                           const float* __restrict__ Wk,
                           const float* __restrict__ Wv) {
    __shared__ unsigned As[64][68];   // [m][k]
    __shared__ unsigned Bs[64][68];   // [k][n]
    const float* W = (blockIdx.z == 0) ? Wq : ((blockIdx.z == 1) ? Wk : Wv);
    float* out = (blockIdx.z == 0) ? g_q : ((blockIdx.z == 1) ? g_kc : g_v);
    const int n0 = blockIdx.x * 64, m0 = blockIdx.y * 64;
    const int tid = threadIdx.x, w = tid >> 5, lane = tid & 31;
    const int wm = w & 1, wn = w >> 1;
    const int gid = lane >> 2, tig = lane & 3;

    float c[2][4][4] = {};
    for (int ch = 0; ch < 4; ch++) {
        const int kb = ch * 64;
#pragma unroll
        for (int i = 0; i < 8; i++) {
            int slot = tid + i * 128;
            int row = slot >> 4, c4 = slot & 15;
            float4 av = *(const float4*)&x[(size_t)(m0 + row) * DIMX + kb + c4 * 4];
            *(uint4*)&As[row][c4 * 4] = f2t4(av);
            float4 bv = *(const float4*)&W[(size_t)(kb + row) * INNER + n0 + c4 * 4];
            *(uint4*)&Bs[row][c4 * 4] = f2t4(bv);
        }
        __syncthreads();
#pragma unroll
        for (int kk = 0; kk < 8; kk++) {
            const int k0 = kk * 8;
            unsigned a[2][4], b[4][2];
#pragma unroll
            for (int am = 0; am < 2; am++) {
                int rb = wm * 32 + am * 16;
                a[am][0] = As[rb + gid][k0 + tig];
                a[am][1] = As[rb + gid + 8][k0 + tig];
                a[am][2] = As[rb + gid][k0 + tig + 4];
                a[am][3] = As[rb + gid + 8][k0 + tig + 4];
            }
#pragma unroll
            for (int an = 0; an < 4; an++) {
                int cb = wn * 32 + an * 8;
                b[an][0] = Bs[k0 + tig][cb + gid];
                b[an][1] = Bs[k0 + tig + 4][cb + gid];
            }
#pragma unroll
            for (int am = 0; am < 2; am++)
#pragma unroll
                for (int an = 0; an < 4; an++)
                    mma8(c[am][an], a[am], b[an]);
        }
        __syncthreads();
    }
#pragma unroll
    for (int am = 0; am < 2; am++) {
        int r0 = m0 + wm * 32 + am * 16 + gid;
#pragma unroll
        for (int an = 0; an < 4; an++) {
            int cc = n0 + wn * 32 + an * 8 + tig * 2;
            *(float2*)&out[(size_t)r0 * INNER + cc] = make_float2(c[am][an][0], c[am][an][1]);
            *(float2*)&out[(size_t)(r0 + 8) * INNER + cc] = make_float2(c[am][an][2], c[am][an][3]);
        }
    }
}

// ---------------- K2: content scores (tf32 mma) ------------------------
// grid (8 jtile, 8 itile, 8 head), block 128, tile 64x64, K=64 single chunk
__global__ void __launch_bounds__(128) cs_kernel() {
    __shared__ unsigned Qs[64][68];   // [i][d]
    __shared__ unsigned Ks[64][68];   // [j][d]
    const int h = blockIdx.z;
    const int j0 = blockIdx.x * 64, i0 = blockIdx.y * 64;
    const int tid = threadIdx.x, w = tid >> 5, lane = tid & 31;
    const int wm = w & 1, wn = w >> 1;
    const int gid = lane >> 2, tig = lane & 3;

#pragma unroll
    for (int i = 0; i < 8; i++) {
        int slot = tid + i * 128;
        int row = slot >> 4, c4 = slot & 15;
        float4 qv = *(const float4*)&g_q [(size_t)(i0 + row) * INNER + h * DH + c4 * 4];
        *(uint4*)&Qs[row][c4 * 4] = f2t4(qv);
        float4 kv = *(const float4*)&g_kc[(size_t)(j0 + row) * INNER + h * DH + c4 * 4];
        *(uint4*)&Ks[row][c4 * 4] = f2t4(kv);
    }
    __syncthreads();

    float c[2][4][4] = {};
#pragma unroll
    for (int kk = 0; kk < 8; kk++) {
        const int k0 = kk * 8;
        unsigned a[2][4], b[4][2];
#pragma unroll
        for (int am = 0; am < 2; am++) {
            int rb = wm * 32 + am * 16;
            a[am][0] = Qs[rb + gid][k0 + tig];
            a[am][1] = Qs[rb + gid + 8][k0 + tig];
            a[am][2] = Qs[rb + gid][k0 + tig + 4];
            a[am][3] = Qs[rb + gid + 8][k0 + tig + 4];
        }
#pragma unroll
        for (int an = 0; an < 4; an++) {
            int cb = wn * 32 + an * 8;
            b[an][0] = Ks[cb + gid][k0 + tig];
            b[an][1] = Ks[cb + gid][k0 + tig + 4];
        }
#pragma unroll
        for (int am = 0; am < 2; am++)
#pragma unroll
            for (int an = 0; an < 4; an++)
                mma8(c[am][an], a[am], b[an]);
    }
#pragma unroll
    for (int am = 0; am < 2; am++) {
        int r0 = i0 + wm * 32 + am * 16 + gid;
#pragma unroll
        for (int an = 0; an < 4; an++) {
            int cc = j0 + wn * 32 + an * 8 + tig * 2;
            float* d0 = &g_sc[((size_t)r0 * NH + h) * NN + cc];
            float* d1 = &g_sc[((size_t)(r0 + 8) * NH + h) * NN + cc];
            *(float2*)d0 = make_float2(c[am][an][0] * SCALE_F, c[am][an][1] * SCALE_F);
            *(float2*)d1 = make_float2(c[am][an][2] * SCALE_F, c[am][an][3] * SCALE_F);
        }
    }
}

// ---------------- K2b: P[i][r][h] (fp32) -------------------------------
// grid 64 (8 queries each), block 256
__global__ void __launch_bounds__(256) p_kernel(const float* __restrict__ Wk) {
    __shared__ float qs[8 * INNER];
    const int tid = threadIdx.x;
    const int i0 = blockIdx.x * 8;
    const float4* src = (const float4*)(g_q + (size_t)i0 * INNER);
#pragma unroll
    for (int u = 0; u < 4; u++) ((float4*)qs)[tid + u * 256] = src[tid + u * 256];
    __syncthreads();
    for (int tt = tid; tt < 528; tt += 256) {
        int r = tt >> 3, h = tt & 7;
        const float4* w4 = (const float4*)(Wk + (size_t)(DIMX + r) * INNER + h * DH);
        float acc[8] = {};
#pragma unroll
        for (int u = 0; u < 16; u++) {
            float4 wv = w4[u];
#pragma unroll
            for (int i = 0; i < 8; i++) {
                float4 qv = *(const float4*)&qs[i * INNER + h * DH + u * 4];
                acc[i] += wv.x*qv.x + wv.y*qv.y + wv.z*qv.z + wv.w*qv.w;
            }
        }
#pragma unroll
        for (int i = 0; i < 8; i++)
            g_P[((size_t)(i0 + i) * NR + r) * NH + h] = acc[i];
    }
}

// ---------------- K3: RPE features + score add + softmax --------------
__global__ void __launch_bounds__(256, 3) rpe_softmax_kernel(const float* __restrict__ pos) {
    const int i = blockIdx.x;
    __shared__ float Ps[NR * NH];
    __shared__ float s_s[NH][NN];
    const int tid = threadIdx.x;
    for (int t = tid; t < NR * NH; t += 256) Ps[t] = g_P[(size_t)i * NR * NH + t];
    __syncthreads();

    const float2* pos2 = reinterpret_cast<const float2*>(pos);
    const float2 pq = pos2[i];
    const float4* Pt4 = reinterpret_cast<const float4*>(Ps);

    const int ja = tid, jb = tid + 256;
    const float2 pka = pos2[ja];
    const float2 pkb = pos2[jb];
    float dxa = (pka.x - pq.x) * INV_NORM; dxa = __fdividef(dxa, 1.f + fabsf(dxa));
    float dya = (pka.y - pq.y) * INV_NORM; dya = __fdividef(dya, 1.f + fabsf(dya));
    float dxb = (pkb.x - pq.x) * INV_NORM; dxb = __fdividef(dxb, 1.f + fabsf(dxb));
    float dyb = (pkb.y - pq.y) * INV_NORM; dyb = __fdividef(dyb, 1.f + fabsf(dyb));

    float A0[8] = {};
    float A1[8] = {};
    {
        float sa, ca, sb, cb, sda, cda, sdb, cdb;
        __sincosf(dxa * PI_F, &sa, &ca);  __sincosf(dxa * DSTEP_F, &sda, &cda);
        __sincosf(dxb * PI_F, &sb, &cb);  __sincosf(dxb * DSTEP_F, &sdb, &cdb);
#pragma unroll
        for (int k = 0; k < 16; k++) {
            float4 p0 = Pt4[2 * k],        p1 = Pt4[2 * k + 1];
            float4 q0 = Pt4[2 * (16 + k)], q1 = Pt4[2 * (16 + k) + 1];
            A0[0] += sa*p0.x + ca*q0.x;  A1[0] += sb*p0.x + cb*q0.x;
            A0[1] += sa*p0.y + ca*q0.y;  A1[1] += sb*p0.y + cb*q0.y;
            A0[2] += sa*p0.z + ca*q0.z;  A1[2] += sb*p0.z + cb*q0.z;
            A0[3] += sa*p0.w + ca*q0.w;  A1[3] += sb*p0.w + cb*q0.w;
            A0[4] += sa*p1.x + ca*q1.x;  A1[4] += sb*p1.x + cb*q1.x;
            A0[5] += sa*p1.y + ca*q1.y;  A1[5] += sb*p1.y + cb*q1.y;
            A0[6] += sa*p1.z + ca*q1.z;  A1[6] += sb*p1.z + cb*q1.z;
            A0[7] += sa*p1.w + ca*q1.w;  A1[7] += sb*p1.w + cb*q1.w;
            float ns = sa*cda + ca*sda, nc = ca*cda - sa*sda; sa = ns; ca = nc;
            ns = sb*cdb + cb*sdb; nc = cb*cdb - sb*sdb; sb = ns; cb = nc;
        }
        float4 p0 = Pt4[64], p1 = Pt4[65];
        A0[0] += dxa*p0.x; A0[1] += dxa*p0.y; A0[2] += dxa*p0.z; A0[3] += dxa*p0.w;
        A0[4] += dxa*p1.x; A0[5] += dxa*p1.y; A0[6] += dxa*p1.z; A0[7] += dxa*p1.w;
        A1[0] += dxb*p0.x; A1[1] += dxb*p0.y; A1[2] += dxb*p0.z; A1[3] += dxb*p0.w;
        A1[4] += dxb*p1.x; A1[5] += dxb*p1.y; A1[6] += dxb*p1.z; A1[7] += dxb*p1.w;
    }
    {
        float sa, ca, sb, cb, sda, cda, sdb, cdb;
        __sincosf(dya * PI_F, &sa, &ca);  __sincosf(dya * DSTEP_F, &sda, &cda);
        __sincosf(dyb * PI_F, &sb, &cb);  __sincosf(dyb * DSTEP_F, &sdb, &cdb);
#pragma unroll
        for (int k = 0; k < 16; k++) {
            float4 p0 = Pt4[2 * (33 + k)], p1 = Pt4[2 * (33 + k) + 1];
            float4 q0 = Pt4[2 * (49 + k)], q1 = Pt4[2 * (49 + k) + 1];
            A0[0] += sa*p0.x + ca*q0.x;  A1[0] += sb*p0.x + cb*q0.x;
            A0[1] += sa*p0.y + ca*q0.y;  A1[1] += sb*p0.y + cb*q0.y;
            A0[2] += sa*p0.z + ca*q0.z;  A1[2] += sb*p0.z + cb*q0.z;
            A0[3] += sa*p0.w + ca*q0.w;  A1[3] += sb*p0.w + cb*q0.w;
            A0[4] += sa*p1.x + ca*q1.x;  A1[4] += sb*p1.x + cb*q1.x;
            A0[5] += sa*p1.y + ca*q1.y;  A1[5] += sb*p1.y + cb*q1.y;
            A0[6] += sa*p1.z + ca*q1.z;  A1[6] += sb*p1.z + cb*q1.z;
            A0[7] += sa*p1.w + ca*q1.w;  A1[7] += sb*p1.w + cb*q1.w;
            float ns = sa*cda + ca*sda, nc = ca*cda - sa*sda; sa = ns; ca = nc;
            ns = sb*cdb + cb*sdb; nc = cb*cdb - sb*sdb; sb = ns; cb = nc;
        }
        float4 p0 = Pt4[130], p1 = Pt4[131];
        A0[0] += dya*p0.x; A0[1] += dya*p0.y; A0[2] += dya*p0.z; A0[3] += dya*p0.w;
        A0[4] += dya*p1.x; A0[5] += dya*p1.y; A0[6] += dya*p1.z; A0[7] += dya*p1.w;
        A1[0] += dyb*p0.x; A1[1] += dyb*p0.y; A1[2] += dyb*p0.z; A1[3] += dyb*p0.w;
        A1[4] += dyb*p1.x; A1[5] += dyb*p1.y; A1[6] += dyb*p1.z; A1[7] += dyb*p1.w;
    }

    const float* csrow = g_sc + (size_t)i * NH * NN;
#pragma unroll
    for (int h = 0; h < NH; h++) {
        s_s[h][ja] = csrow[h * NN + ja] + A0[h] * SCALE_F;
        s_s[h][jb] = csrow[h * NN + jb] + A1[h] * SCALE_F;
    }
    __syncthreads();

    const int w = tid >> 5, lane = tid & 31;
    float m = -CUDART_INF_F;
    for (int j = lane; j < NN; j += 32) m = fmaxf(m, s_s[w][j]);
#pragma unroll
    for (int o = 16; o; o >>= 1) m = fmaxf(m, __shfl_xor_sync(0xffffffffu, m, o));
    float sum = 0.f;
    for (int j = lane; j < NN; j += 32) {
        float e = __expf(s_s[w][j] - m);
        s_s[w][j] = e;
        sum += e;
    }
#pragma unroll
    for (int o = 16; o; o >>= 1) sum += __shfl_xor_sync(0xffffffffu, sum, o);
    const float inv = __fdividef(1.0f, sum);
    float* arow = g_sc + (size_t)i * NH * NN + (size_t)w * NN;
    for (int j = lane; j < NN; j += 32)
        arow[j] = s_s[w][j] * inv;
}

// ---------------- K4: attn @ V (tf32 mma), split-K=4 -------------------
// grid (8 itile, 8 head, 4 split), block 128, tile 64x64, K=128 in 2 chunks
__global__ void __launch_bounds__(128) av_kernel() {
    __shared__ unsigned At[64][68];   // [i][j]
    __shared__ unsigned Vs[64][68];   // [j][d]
    const int i0 = blockIdx.x * 64;
    const int h  = blockIdx.y;
    const int s  = blockIdx.z;
    const int kbase = s * 128;
    const int tid = threadIdx.x, w = tid >> 5, lane = tid & 31;
    const int wm = w & 1, wn = w >> 1;
    const int gid = lane >> 2, tig = lane & 3;

    float c[2][4][4] = {};
    for (int ch = 0; ch < 2; ch++) {
        const int kb = kbase + ch * 64;
#pragma unroll
        for (int i = 0; i < 8; i++) {
            int slot = tid + i * 128;
            int row = slot >> 4, c4 = slot & 15;
            float4 av = *(const float4*)&g_sc[((size_t)(i0 + row) * NH + h) * NN + kb + c4 * 4];
            *(uint4*)&At[row][c4 * 4] = f2t4(av);
            float4 vv = *(const float4*)&g_v[(size_t)(kb + row) * INNER + h * DH + c4 * 4];
            *(uint4*)&Vs[row][c4 * 4] = f2t4(vv);
        }
        __syncthreads();
#pragma unroll
        for (int kk = 0; kk < 8; kk++) {
            const int k0 = kk * 8;
            unsigned a[2][4], b[4][2];
#pragma unroll
            for (int am = 0; am < 2; am++) {
                int rb = wm * 32 + am * 16;
                a[am][0] = At[rb + gid][k0 + tig];
                a[am][1] = At[rb + gid + 8][k0 + tig];
                a[am][2] = At[rb + gid][k0 + tig + 4];
                a[am][3] = At[rb + gid + 8][k0 + tig + 4];
            }
#pragma unroll
            for (int an = 0; an < 4; an++) {
                int cb = wn * 32 + an * 8;
                b[an][0] = Vs[k0 + tig][cb + gid];
                b[an][1] = Vs[k0 + tig + 4][cb + gid];
            }
#pragma unroll
            for (int am = 0; am < 2; am++)
#pragma unroll
                for (int an = 0; an < 4; an++)
                    mma8(c[am][an], a[am], b[an]);
        }
        __syncthreads();
    }
#pragma unroll
    for (int am = 0; am < 2; am++) {
        int r0 = i0 + wm * 32 + am * 16 + gid;
#pragma unroll
        for (int an = 0; an < 4; an++) {
            int cc = h * DH + wn * 32 + an * 8 + tig * 2;
            float* d0 = &g_ao[((size_t)s * NN + r0) * INNER + cc];
            float* d1 = &g_ao[((size_t)s * NN + r0 + 8) * INNER + cc];
            *(float2*)d0 = make_float2(c[am][an][0], c[am][an][1]);
            *(float2*)d1 = make_float2(c[am][an][2], c[am][an][3]);
        }
    }
}

// ---------------- K5: out = (sum_s ao_s) @ Wo + bo, 16x64 tile ---------
__global__ void __launch_bounds__(256) out_kernel(const float* __restrict__ Wo,
                           const float* __restrict__ bo,
                           float* __restrict__ out) {
    const int n0 = blockIdx.x * 64;
    const int i0 = blockIdx.y * 16;
    __shared__ float At[64][17];
    __shared__ float Bt[64][68];
    const int tid = threadIdx.x;
    const int ti = tid >> 4, tn = tid & 15;
    const int ak = tid & 15;
    const int bkr = tid >> 2, bc2 = tid & 3;
    const float* arow = g_ao + (size_t)(i0 + ti) * INNER;
    const float* wrow = Wo + n0;

    float4 pa;
    {
        float4 u0 = *(const float4*)&arow[ak * 4];
        float4 u1 = *(const float4*)&arow[(size_t)NN * INNER + ak * 4];
        float4 u2 = *(const float4*)&arow[2 * (size_t)NN * INNER + ak * 4];
        float4 u3 = *(const float4*)&arow[3 * (size_t)NN * INNER + ak * 4];
        pa = make_float4(u0.x+u1.x+u2.x+u3.x, u0.y+u1.y+u2.y+u3.y,
                         u0.z+u1.z+u2.z+u3.z, u0.w+u1.w+u2.w+u3.w);
    }
    float4 pb[4];
#pragma unroll
    for (int u = 0; u < 4; u++)
        pb[u] = *(const float4*)&wrow[(size_t)bkr * DIMX + (bc2 + 4 * u) * 4];

    float acc[4] = {};
    for (int c = 0; c < 8; c++) {
        At[ak*4+0][ti] = pa.x; At[ak*4+1][ti] = pa.y;
        At[ak*4+2][ti] = pa.z; At[ak*4+3][ti] = pa.w;
#pragma unroll
        for (int u = 0; u < 4; u++)
            *(float4*)&Bt[bkr][(bc2 + 4 * u) * 4] = pb[u];
        __syncthreads();
        if (c < 7) {
            int k0 = (c + 1) * 64;
            float4 u0 = *(const float4*)&arow[k0 + ak * 4];
            float4 u1 = *(const float4*)&arow[(size_t)NN * INNER + k0 + ak * 4];
            float4 u2 = *(const float4*)&arow[2 * (size_t)NN * INNER + k0 + ak * 4];
            float4 u3 = *(const float4*)&arow[3 * (size_t)NN * INNER + k0 + ak * 4];
            pa = make_float4(u0.x+u1.x+u2.x+u3.x, u0.y+u1.y+u2.y+u3.y,
                             u0.z+u1.z+u2.z+u3.z, u0.w+u1.w+u2.w+u3.w);
#pragma unroll
            for (int u = 0; u < 4; u++)
                pb[u] = *(const float4*)&wrow[(size_t)(k0 + bkr) * DIMX + (bc2 + 4 * u) * 4];
        }
#pragma unroll
        for (int kk = 0; kk < 64; kk++) {
            float a = At[kk][ti];
            float4 b = *(const float4*)&Bt[kk][tn * 4];
            acc[0] += a * b.x; acc[1] += a * b.y;
            acc[2] += a * b.z; acc[3] += a * b.w;
        }
        __syncthreads();
    }
    float4 bv = *(const float4*)&bo[n0 + tn * 4];
    float4 r = make_float4(acc[0] + bv.x, acc[1] + bv.y, acc[2] + bv.z, acc[3] + bv.w);
    *(float4*)&out[(size_t)(i0 + ti) * DIMX + n0 + tn * 4] = r;
}

// ---------------- launch ----------------------------------------------
extern "C" void kernel_launch(void* const* d_in, const int* in_sizes, int n_in,
                              void* d_out, int out_size) {
    const float* x   = (const float*)d_in[0];
    const float* pos = (const float*)d_in[1];
    const float* Wq  = (const float*)d_in[2];
    const float* Wk  = (const float*)d_in[3];
    const float* Wv  = (const float*)d_in[4];
    const float* Wo  = (const float*)d_in[5];
    const float* bo  = (const float*)d_in[6];
    float* out = (float*)d_out;

    qkv_kernel<<<dim3(8, 8, 3), 128>>>(x, Wq, Wk, Wv);
    cs_kernel<<<dim3(8, 8, 8), 128>>>();
    p_kernel<<<64, 256>>>(Wk);
    rpe_softmax_kernel<<<512, 256>>>(pos);
    av_kernel<<<dim3(8, 8, KSPLIT), 128>>>();
    out_kernel<<<dim3(4, 32), 256>>>(Wo, bo, out);
}

// round 7
// speedup vs baseline: 1.3172x; 1.1213x over previous
#include <cuda_runtime.h>
#include <math_constants.h>

#define NN 512
#define DIMX 256
#define NH 8
#define DH 64
#define INNER 512
#define NR 66
#define PI_F 3.14159265358979f
#define SCALE_F 0.125f
#define INV_NORM (1.0f/51.0f)
#define DSTEP_F (7.0f*PI_F/15.0f)
#define KSPLIT 4

typedef unsigned long long ull;

// ---------------- scratch ----------------
__device__ float g_q [NN*INNER];
__device__ float g_kc[NN*INNER];
__device__ float g_v [NN*INNER];
__device__ float g_P [NN*NR*NH];                 // [i][r][h]
__device__ float g_sc[(size_t)NN*NH*NN];         // scores/attn, [i][h][j]
__device__ float g_ao[KSPLIT*(size_t)NN*INNER];  // split-K partials [s][i][hd]

// ---------------- tf32 mma helpers ------------------------------------
static __device__ __forceinline__ unsigned f2t(float x) {
    unsigned u;
    asm("cvt.rna.tf32.f32 %0, %1;" : "=r"(u) : "f"(x));
    return u;
}
static __device__ __forceinline__ void mma8(float* c, const unsigned* a, const unsigned* b) {
    asm volatile(
        "mma.sync.aligned.m16n8k8.row.col.f32.tf32.tf32.f32 "
        "{%0,%1,%2,%3}, {%4,%5,%6,%7}, {%8,%9}, {%0,%1,%2,%3};"
        : "+f"(c[0]), "+f"(c[1]), "+f"(c[2]), "+f"(c[3])
        : "r"(a[0]), "r"(a[1]), "r"(a[2]), "r"(a[3]), "r"(b[0]), "r"(b[1]));
}
static __device__ __forceinline__ uint4 f2t4(float4 v) {
    return make_uint4(f2t(v.x), f2t(v.y), f2t(v.z), f2t(v.w));
}

// ---------------- f32x2 packed helpers ---------------------------------
static __device__ __forceinline__ ull pk2(float x) {
    ull d; unsigned u = __float_as_uint(x);
    asm("mov.b64 %0, {%1, %1};" : "=l"(d) : "r"(u));
    return d;
}
static __device__ __forceinline__ ull fma2(ull a, ull b, ull c) {
    ull d;
    asm("fma.rn.f32x2 %0, %1, %2, %3;" : "=l"(d) : "l"(a), "l"(b), "l"(c));
    return d;
}
static __device__ __forceinline__ float2 up2(ull d) {
    unsigned lo, hi;
    asm("mov.b64 {%0, %1}, %2;" : "=r"(lo), "=r"(hi) : "l"(d));
    return make_float2(__uint_as_float(lo), __uint_as_float(hi));
}

// ---------------- K1: QKV projections (tf32 mma) -----------------------
__global__ void __launch_bounds__(128) qkv_kernel(const float* __restrict__ x,
                           const float* __restrict__ Wq,
                           const float* __restrict__ Wk,
                           const float* __restrict__ Wv) {
    __shared__ unsigned As[64][68];   // [m][k]
    __shared__ unsigned Bs[64][68];   // [k][n]
    const float* W = (blockIdx.z == 0) ? Wq : ((blockIdx.z == 1) ? Wk : Wv);
    float* out = (blockIdx.z == 0) ? g_q : ((blockIdx.z == 1) ? g_kc : g_v);
    const int n0 = blockIdx.x * 64, m0 = blockIdx.y * 64;
    const int tid = threadIdx.x, w = tid >> 5, lane = tid & 31;
    const int wm = w & 1, wn = w >> 1;
    const int gid = lane >> 2, tig = lane & 3;

    float c[2][4][4] = {};
    for (int ch = 0; ch < 4; ch++) {
        const int kb = ch * 64;
#pragma unroll
        for (int i = 0; i < 8; i++) {
            int slot = tid + i * 128;
            int row = slot >> 4, c4 = slot & 15;
            float4 av = *(const float4*)&x[(size_t)(m0 + row) * DIMX + kb + c4 * 4];
            *(uint4*)&As[row][c4 * 4] = f2t4(av);
            float4 bv = *(const float4*)&W[(size_t)(kb + row) * INNER + n0 + c4 * 4];
            *(uint4*)&Bs[row][c4 * 4] = f2t4(bv);
        }
        __syncthreads();
#pragma unroll
        for (int kk = 0; kk < 8; kk++) {
            const int k0 = kk * 8;
            unsigned a[2][4], b[4][2];
#pragma unroll
            for (int am = 0; am < 2; am++) {
                int rb = wm * 32 + am * 16;
                a[am][0] = As[rb + gid][k0 + tig];
                a[am][1] = As[rb + gid + 8][k0 + tig];
                a[am][2] = As[rb + gid][k0 + tig + 4];
                a[am][3] = As[rb + gid + 8][k0 + tig + 4];
            }
#pragma unroll
            for (int an = 0; an < 4; an++) {
                int cb = wn * 32 + an * 8;
                b[an][0] = Bs[k0 + tig][cb + gid];
                b[an][1] = Bs[k0 + tig + 4][cb + gid];
            }
#pragma unroll
            for (int am = 0; am < 2; am++)
#pragma unroll
                for (int an = 0; an < 4; an++)
                    mma8(c[am][an], a[am], b[an]);
        }
        __syncthreads();
    }
#pragma unroll
    for (int am = 0; am < 2; am++) {
        int r0 = m0 + wm * 32 + am * 16 + gid;
#pragma unroll
        for (int an = 0; an < 4; an++) {
            int cc = n0 + wn * 32 + an * 8 + tig * 2;
            *(float2*)&out[(size_t)r0 * INNER + cc] = make_float2(c[am][an][0], c[am][an][1]);
            *(float2*)&out[(size_t)(r0 + 8) * INNER + cc] = make_float2(c[am][an][2], c[am][an][3]);
        }
    }
}

// ---------------- K2: content scores (tf32 mma) ------------------------
__global__ void __launch_bounds__(128) cs_kernel() {
    __shared__ unsigned Qs[64][68];
    __shared__ unsigned Ks[64][68];
    const int h = blockIdx.z;
    const int j0 = blockIdx.x * 64, i0 = blockIdx.y * 64;
    const int tid = threadIdx.x, w = tid >> 5, lane = tid & 31;
    const int wm = w & 1, wn = w >> 1;
    const int gid = lane >> 2, tig = lane & 3;

#pragma unroll
    for (int i = 0; i < 8; i++) {
        int slot = tid + i * 128;
        int row = slot >> 4, c4 = slot & 15;
        float4 qv = *(const float4*)&g_q [(size_t)(i0 + row) * INNER + h * DH + c4 * 4];
        *(uint4*)&Qs[row][c4 * 4] = f2t4(qv);
        float4 kv = *(const float4*)&g_kc[(size_t)(j0 + row) * INNER + h * DH + c4 * 4];
        *(uint4*)&Ks[row][c4 * 4] = f2t4(kv);
    }
    __syncthreads();

    float c[2][4][4] = {};
#pragma unroll
    for (int kk = 0; kk < 8; kk++) {
        const int k0 = kk * 8;
        unsigned a[2][4], b[4][2];
#pragma unroll
        for (int am = 0; am < 2; am++) {
            int rb = wm * 32 + am * 16;
            a[am][0] = Qs[rb + gid][k0 + tig];
            a[am][1] = Qs[rb + gid + 8][k0 + tig];
            a[am][2] = Qs[rb + gid][k0 + tig + 4];
            a[am][3] = Qs[rb + gid + 8][k0 + tig + 4];
        }
#pragma unroll
        for (int an = 0; an < 4; an++) {
            int cb = wn * 32 + an * 8;
            b[an][0] = Ks[cb + gid][k0 + tig];
            b[an][1] = Ks[cb + gid][k0 + tig + 4];
        }
#pragma unroll
        for (int am = 0; am < 2; am++)
#pragma unroll
            for (int an = 0; an < 4; an++)
                mma8(c[am][an], a[am], b[an]);
    }
#pragma unroll
    for (int am = 0; am < 2; am++) {
        int r0 = i0 + wm * 32 + am * 16 + gid;
#pragma unroll
        for (int an = 0; an < 4; an++) {
            int cc = j0 + wn * 32 + an * 8 + tig * 2;
            float* d0 = &g_sc[((size_t)r0 * NH + h) * NN + cc];
            float* d1 = &g_sc[((size_t)(r0 + 8) * NH + h) * NN + cc];
            *(float2*)d0 = make_float2(c[am][an][0] * SCALE_F, c[am][an][1] * SCALE_F);
            *(float2*)d1 = make_float2(c[am][an][2] * SCALE_F, c[am][an][3] * SCALE_F);
        }
    }
}

// ---------------- K2b: P[i][r][h] (fp32), 256 blocks x 2 queries -------
__global__ void __launch_bounds__(256) p_kernel(const float* __restrict__ Wk) {
    __shared__ float qs[2 * INNER];
    const int tid = threadIdx.x;
    const int i0 = blockIdx.x * 2;
    const float4* src = (const float4*)(g_q + (size_t)i0 * INNER);
    ((float4*)qs)[tid] = src[tid];
    __syncthreads();
    for (int tt = tid; tt < 528; tt += 256) {
        int r = tt >> 3, h = tt & 7;
        const float4* w4 = (const float4*)(Wk + (size_t)(DIMX + r) * INNER + h * DH);
        float acc0 = 0.f, acc1 = 0.f;
#pragma unroll
        for (int u = 0; u < 16; u++) {
            float4 wv = w4[u];
            float4 q0 = *(const float4*)&qs[h * DH + u * 4];
            float4 q1 = *(const float4*)&qs[INNER + h * DH + u * 4];
            acc0 += wv.x*q0.x + wv.y*q0.y + wv.z*q0.z + wv.w*q0.w;
            acc1 += wv.x*q1.x + wv.y*q1.y + wv.z*q1.z + wv.w*q1.w;
        }
        g_P[((size_t)i0 * NR + r) * NH + h] = acc0;
        g_P[((size_t)(i0 + 1) * NR + r) * NH + h] = acc1;
    }
}

// ---------------- K3: RPE features + score add + softmax (f32x2) ------
__global__ void __launch_bounds__(256, 3) rpe_softmax_kernel(const float* __restrict__ pos) {
    const int i = blockIdx.x;
    __shared__ float Ps[NR * NH];
    __shared__ float s_s[NH][NN];
    const int tid = threadIdx.x;
    for (int t = tid; t < NR * NH; t += 256) Ps[t] = g_P[(size_t)i * NR * NH + t];
    __syncthreads();

    const float2* pos2 = reinterpret_cast<const float2*>(pos);
    const float2 pq = pos2[i];
    const ulonglong2* Pu2 = reinterpret_cast<const ulonglong2*>(Ps);  // 2 per row (8 floats)

    const int ja = tid, jb = tid + 256;
    const float2 pka = pos2[ja];
    const float2 pkb = pos2[jb];
    float dxa = (pka.x - pq.x) * INV_NORM; dxa = __fdividef(dxa, 1.f + fabsf(dxa));
    float dya = (pka.y - pq.y) * INV_NORM; dya = __fdividef(dya, 1.f + fabsf(dya));
    float dxb = (pkb.x - pq.x) * INV_NORM; dxb = __fdividef(dxb, 1.f + fabsf(dxb));
    float dyb = (pkb.y - pq.y) * INV_NORM; dyb = __fdividef(dyb, 1.f + fabsf(dyb));

    ull A0v[4] = {}, A1v[4] = {};  // packed head-pair accumulators

    // ---- x axis: sin rows k, cos rows 16+k, identity row 32 ----
    {
        float sa, ca, sb, cb, sda, cda, sdb, cdb;
        __sincosf(dxa * PI_F, &sa, &ca);  __sincosf(dxa * DSTEP_F, &sda, &cda);
        __sincosf(dxb * PI_F, &sb, &cb);  __sincosf(dxb * DSTEP_F, &sdb, &cdb);
#pragma unroll
        for (int k = 0; k < 16; k++) {
            ulonglong2 pA = Pu2[2 * k],        pB = Pu2[2 * k + 1];
            ulonglong2 qA = Pu2[2 * (16 + k)], qB = Pu2[2 * (16 + k) + 1];
            ull sa2 = pk2(sa), ca2 = pk2(ca), sb2 = pk2(sb), cb2 = pk2(cb);
            A0v[0] = fma2(sa2, pA.x, A0v[0]); A0v[1] = fma2(sa2, pA.y, A0v[1]);
            A0v[2] = fma2(sa2, pB.x, A0v[2]); A0v[3] = fma2(sa2, pB.y, A0v[3]);
            A0v[0] = fma2(ca2, qA.x, A0v[0]); A0v[1] = fma2(ca2, qA.y, A0v[1]);
            A0v[2] = fma2(ca2, qB.x, A0v[2]); A0v[3] = fma2(ca2, qB.y, A0v[3]);
            A1v[0] = fma2(sb2, pA.x, A1v[0]); A1v[1] = fma2(sb2, pA.y, A1v[1]);
            A1v[2] = fma2(sb2, pB.x, A1v[2]); A1v[3] = fma2(sb2, pB.y, A1v[3]);
            A1v[0] = fma2(cb2, qA.x, A1v[0]); A1v[1] = fma2(cb2, qA.y, A1v[1]);
            A1v[2] = fma2(cb2, qB.x, A1v[2]); A1v[3] = fma2(cb2, qB.y, A1v[3]);
            float ns = sa*cda + ca*sda, nc = ca*cda - sa*sda; sa = ns; ca = nc;
            ns = sb*cdb + cb*sdb; nc = cb*cdb - sb*sdb; sb = ns; cb = nc;
        }
        ulonglong2 pA = Pu2[2 * 32], pB = Pu2[2 * 32 + 1];
        ull da2 = pk2(dxa), db2 = pk2(dxb);
        A0v[0] = fma2(da2, pA.x, A0v[0]); A0v[1] = fma2(da2, pA.y, A0v[1]);
        A0v[2] = fma2(da2, pB.x, A0v[2]); A0v[3] = fma2(da2, pB.y, A0v[3]);
        A1v[0] = fma2(db2, pA.x, A1v[0]); A1v[1] = fma2(db2, pA.y, A1v[1]);
        A1v[2] = fma2(db2, pB.x, A1v[2]); A1v[3] = fma2(db2, pB.y, A1v[3]);
    }
    // ---- y axis: sin rows 33+k, cos rows 49+k, identity row 65 ----
    {
        float sa, ca, sb, cb, sda, cda, sdb, cdb;
        __sincosf(dya * PI_F, &sa, &ca);  __sincosf(dya * DSTEP_F, &sda, &cda);
        __sincosf(dyb * PI_F, &sb, &cb);  __sincosf(dyb * DSTEP_F, &sdb, &cdb);
#pragma unroll
        for (int k = 0; k < 16; k++) {
            ulonglong2 pA = Pu2[2 * (33 + k)], pB = Pu2[2 * (33 + k) + 1];
            ulonglong2 qA = Pu2[2 * (49 + k)], qB = Pu2[2 * (49 + k) + 1];
            ull sa2 = pk2(sa), ca2 = pk2(ca), sb2 = pk2(sb), cb2 = pk2(cb);
            A0v[0] = fma2(sa2, pA.x, A0v[0]); A0v[1] = fma2(sa2, pA.y, A0v[1]);
            A0v[2] = fma2(sa2, pB.x, A0v[2]); A0v[3] = fma2(sa2, pB.y, A0v[3]);
            A0v[0] = fma2(ca2, qA.x, A0v[0]); A0v[1] = fma2(ca2, qA.y, A0v[1]);
            A0v[2] = fma2(ca2, qB.x, A0v[2]); A0v[3] = fma2(ca2, qB.y, A0v[3]);
            A1v[0] = fma2(sb2, pA.x, A1v[0]); A1v[1] = fma2(sb2, pA.y, A1v[1]);
            A1v[2] = fma2(sb2, pB.x, A1v[2]); A1v[3] = fma2(sb2, pB.y, A1v[3]);
            A1v[0] = fma2(cb2, qA.x, A1v[0]); A1v[1] = fma2(cb2, qA.y, A1v[1]);
            A1v[2] = fma2(cb2, qB.x, A1v[2]); A1v[3] = fma2(cb2, qB.y, A1v[3]);
            float ns = sa*cda + ca*sda, nc = ca*cda - sa*sda; sa = ns; ca = nc;
            ns = sb*cdb + cb*sdb; nc = cb*cdb - sb*sdb; sb = ns; cb = nc;
        }
        ulonglong2 pA = Pu2[2 * 65], pB = Pu2[2 * 65 + 1];
        ull da2 = pk2(dya), db2 = pk2(dyb);
        A0v[0] = fma2(da2, pA.x, A0v[0]); A0v[1] = fma2(da2, pA.y, A0v[1]);
        A0v[2] = fma2(da2, pB.x, A0v[2]); A0v[3] = fma2(da2, pB.y, A0v[3]);
        A1v[0] = fma2(db2, pA.x, A1v[0]); A1v[1] = fma2(db2, pA.y, A1v[1]);
        A1v[2] = fma2(db2, pB.x, A1v[2]); A1v[3] = fma2(db2, pB.y, A1v[3]);
    }

    const float* csrow = g_sc + (size_t)i * NH * NN;
#pragma unroll
    for (int hp = 0; hp < 4; hp++) {
        float2 a0 = up2(A0v[hp]);
        float2 a1 = up2(A1v[hp]);
        int h0 = hp * 2, h1 = hp * 2 + 1;
        s_s[h0][ja] = csrow[h0 * NN + ja] + a0.x * SCALE_F;
        s_s[h1][ja] = csrow[h1 * NN + ja] + a0.y * SCALE_F;
        s_s[h0][jb] = csrow[h0 * NN + jb] + a1.x * SCALE_F;
        s_s[h1][jb] = csrow[h1 * NN + jb] + a1.y * SCALE_F;
    }
    __syncthreads();

    const int w = tid >> 5, lane = tid & 31;
    float m = -CUDART_INF_F;
    for (int j = lane; j < NN; j += 32) m = fmaxf(m, s_s[w][j]);
#pragma unroll
    for (int o = 16; o; o >>= 1) m = fmaxf(m, __shfl_xor_sync(0xffffffffu, m, o));
    float sum = 0.f;
    for (int j = lane; j < NN; j += 32) {
        float e = __expf(s_s[w][j] - m);
        s_s[w][j] = e;
        sum += e;
    }
#pragma unroll
    for (int o = 16; o; o >>= 1) sum += __shfl_xor_sync(0xffffffffu, sum, o);
    const float inv = __fdividef(1.0f, sum);
    float* arow = g_sc + (size_t)i * NH * NN + (size_t)w * NN;
    for (int j = lane; j < NN; j += 32)
        arow[j] = s_s[w][j] * inv;
}

// ---------------- K4: attn @ V (tf32 mma), split-K=4 -------------------
__global__ void __launch_bounds__(128) av_kernel() {
    __shared__ unsigned At[64][68];
    __shared__ unsigned Vs[64][68];
    const int i0 = blockIdx.x * 64;
    const int h  = blockIdx.y;
    const int s  = blockIdx.z;
    const int kbase = s * 128;
    const int tid = threadIdx.x, w = tid >> 5, lane = tid & 31;
    const int wm = w & 1, wn = w >> 1;
    const int gid = lane >> 2, tig = lane & 3;

    float c[2][4][4] = {};
    for (int ch = 0; ch < 2; ch++) {
        const int kb = kbase + ch * 64;
#pragma unroll
        for (int i = 0; i < 8; i++) {
            int slot = tid + i * 128;
            int row = slot >> 4, c4 = slot & 15;
            float4 av = *(const float4*)&g_sc[((size_t)(i0 + row) * NH + h) * NN + kb + c4 * 4];
            *(uint4*)&At[row][c4 * 4] = f2t4(av);
            float4 vv = *(const float4*)&g_v[(size_t)(kb + row) * INNER + h * DH + c4 * 4];
            *(uint4*)&Vs[row][c4 * 4] = f2t4(vv);
        }
        __syncthreads();
#pragma unroll
        for (int kk = 0; kk < 8; kk++) {
            const int k0 = kk * 8;
            unsigned a[2][4], b[4][2];
#pragma unroll
            for (int am = 0; am < 2; am++) {
                int rb = wm * 32 + am * 16;
                a[am][0] = At[rb + gid][k0 + tig];
                a[am][1] = At[rb + gid + 8][k0 + tig];
                a[am][2] = At[rb + gid][k0 + tig + 4];
                a[am][3] = At[rb + gid + 8][k0 + tig + 4];
            }
#pragma unroll
            for (int an = 0; an < 4; an++) {
                int cb = wn * 32 + an * 8;
                b[an][0] = Vs[k0 + tig][cb + gid];
                b[an][1] = Vs[k0 + tig + 4][cb + gid];
            }
#pragma unroll
            for (int am = 0; am < 2; am++)
#pragma unroll
                for (int an = 0; an < 4; an++)
                    mma8(c[am][an], a[am], b[an]);
        }
        __syncthreads();
    }
#pragma unroll
    for (int am = 0; am < 2; am++) {
        int r0 = i0 + wm * 32 + am * 16 + gid;
#pragma unroll
        for (int an = 0; an < 4; an++) {
            int cc = h * DH + wn * 32 + an * 8 + tig * 2;
            float* d0 = &g_ao[((size_t)s * NN + r0) * INNER + cc];
            float* d1 = &g_ao[((size_t)s * NN + r0 + 8) * INNER + cc];
            *(float2*)d0 = make_float2(c[am][an][0], c[am][an][1]);
            *(float2*)d1 = make_float2(c[am][an][2], c[am][an][3]);
        }
    }
}

// ---------------- K5: out = (sum_s ao_s) @ Wo + bo (tf32 mma) ----------
// grid (4 ntile, 16 mtile), block 128, tile 32x64, K=512 in 8 chunks
__global__ void __launch_bounds__(128) out_kernel(const float* __restrict__ Wo,
                           const float* __restrict__ bo,
                           float* __restrict__ out) {
    __shared__ unsigned As[32][68];   // [m][k]
    __shared__ unsigned Bs[64][68];   // [k][n]
    const int n0 = blockIdx.x * 64;
    const int i0 = blockIdx.y * 32;
    const int tid = threadIdx.x, w = tid >> 5, lane = tid & 31;
    const int wm = w & 1, wn = w >> 1;
    const int gid = lane >> 2, tig = lane & 3;

    float c[4][4] = {};
    for (int ch = 0; ch < 8; ch++) {
        const int kb = ch * 64;
#pragma unroll
        for (int i = 0; i < 4; i++) {
            int slot = tid + i * 128;
            int row = slot >> 4, c4 = slot & 15;
            const float* base = g_ao + (size_t)(i0 + row) * INNER + kb + c4 * 4;
            float4 u0 = *(const float4*)(base);
            float4 u1 = *(const float4*)(base + (size_t)NN * INNER);
            float4 u2 = *(const float4*)(base + 2 * (size_t)NN * INNER);
            float4 u3 = *(const float4*)(base + 3 * (size_t)NN * INNER);
            float4 sum = make_float4(u0.x+u1.x+u2.x+u3.x, u0.y+u1.y+u2.y+u3.y,
                                     u0.z+u1.z+u2.z+u3.z, u0.w+u1.w+u2.w+u3.w);
            *(uint4*)&As[row][c4 * 4] = f2t4(sum);
        }
#pragma unroll
        for (int i = 0; i < 8; i++) {
            int slot = tid + i * 128;
            int row = slot >> 4, c4 = slot & 15;
            float4 bv = *(const float4*)&Wo[(size_t)(kb + row) * DIMX + n0 + c4 * 4];
            *(uint4*)&Bs[row][c4 * 4] = f2t4(bv);
        }
        __syncthreads();
#pragma unroll
        for (int kk = 0; kk < 8; kk++) {
            const int k0 = kk * 8;
            unsigned a[4], b[4][2];
            int rb = wm * 16;
            a[0] = As[rb + gid][k0 + tig];
            a[1] = As[rb + gid + 8][k0 + tig];
            a[2] = As[rb + gid][k0 + tig + 4];
            a[3] = As[rb + gid + 8][k0 + tig + 4];
#pragma unroll
            for (int an = 0; an < 4; an++) {
                int cb = wn * 32 + an * 8;
                b[an][0] = Bs[k0 + tig][cb + gid];
                b[an][1] = Bs[k0 + tig + 4][cb + gid];
            }
#pragma unroll
            for (int an = 0; an < 4; an++)
                mma8(c[an], a, b[an]);
        }
        __syncthreads();
    }
    int r0 = i0 + wm * 16 + gid;
#pragma unroll
    for (int an = 0; an < 4; an++) {
        int cc = n0 + wn * 32 + an * 8 + tig * 2;
        float b0 = bo[cc], b1 = bo[cc + 1];
        *(float2*)&out[(size_t)r0 * DIMX + cc] = make_float2(c[an][0] + b0, c[an][1] + b1);
        *(float2*)&out[(size_t)(r0 + 8) * DIMX + cc] = make_float2(c[an][2] + b0, c[an][3] + b1);
    }
}

// ---------------- launch ----------------------------------------------
extern "C" void kernel_launch(void* const* d_in, const int* in_sizes, int n_in,
                              void* d_out, int out_size) {
    const float* x   = (const float*)d_in[0];
    const float* pos = (const float*)d_in[1];
    const float* Wq  = (const float*)d_in[2];
    const float* Wk  = (const float*)d_in[3];
    const float* Wv  = (const float*)d_in[4];
    const float* Wo  = (const float*)d_in[5];
    const float* bo  = (const float*)d_in[6];
    float* out = (float*)d_out;

    qkv_kernel<<<dim3(8, 8, 3), 128>>>(x, Wq, Wk, Wv);
    cs_kernel<<<dim3(8, 8, 8), 128>>>();
    p_kernel<<<256, 256>>>(Wk);
    rpe_softmax_kernel<<<512, 256>>>(pos);
    av_kernel<<<dim3(8, 8, KSPLIT), 128>>>();
    out_kernel<<<dim3(4, 16), 128>>>(Wo, bo, out);
}